// round 1
// baseline (speedup 1.0000x reference)
#include <cuda_runtime.h>
#include <math_constants.h>

#define EPS_WH 1e-07f
#define MAX_WH 10000000.0f
#define THREADS 256

// Per-batch partial losses (B = 1024 in this problem; padded for safety).
__device__ float g_partial[4096];

__device__ __forceinline__ float clip_wh(float v) {
    return fminf(fmaxf(v, EPS_WH), MAX_WH);
}

// One block per batch element: argmax over HW heatmap values, then gather
// 4 floats + compute the closed-form GWD loss for this batch element.
__global__ void __launch_bounds__(THREADS)
gwd_main_kernel(const float* __restrict__ hm,
                const float* __restrict__ ab,
                const float* __restrict__ trig,
                const float* __restrict__ center,
                const float* __restrict__ target,
                int HW)
{
    const int b = blockIdx.x;
    const int t = threadIdx.x;

    // ---- argmax over hm[b, 0, :] (sigmoid is monotone -> same argmax) ----
    const float4* hm4 = reinterpret_cast<const float4*>(hm + (size_t)b * HW);
    const int n4 = HW >> 2;

    float best = -CUDART_INF_F;
    int bidx = 0;
    #pragma unroll 4
    for (int i = t; i < n4; i += THREADS) {
        float4 v = hm4[i];
        int base = i << 2;
        if (v.x > best) { best = v.x; bidx = base; }
        if (v.y > best) { best = v.y; bidx = base + 1; }
        if (v.z > best) { best = v.z; bidx = base + 2; }
        if (v.w > best) { best = v.w; bidx = base + 3; }
    }

    __shared__ float sv[THREADS];
    __shared__ int   si[THREADS];
    sv[t] = best; si[t] = bidx;
    __syncthreads();
    #pragma unroll
    for (int s = THREADS / 2; s > 0; s >>= 1) {
        if (t < s) {
            float v2 = sv[t + s]; int i2 = si[t + s];
            if (v2 > sv[t] || (v2 == sv[t] && i2 < si[t])) { sv[t] = v2; si[t] = i2; }
        }
        __syncthreads();
    }

    if (t == 0) {
        const int idx = si[0];

        // ---- gather (4 scattered loads instead of streaming 268 MB) ----
        const float* abb = ab   + (size_t)b * 2 * HW;
        const float* tgb = trig + (size_t)b * 2 * HW;
        float a1    = abb[idx];
        float a2    = abb[HW + idx];
        float sin2A = tgb[idx];
        float cos2A = tgb[HW + idx];

        // pred box: deg roundtrip in the reference is identity, keep radians
        float r_p = 0.5f * atan2f(sin2A, cos2A);
        float xp = center[2 * b], yp = center[2 * b + 1];
        float wp = clip_wh(2.0f * a1);
        float hp = clip_wh(2.0f * a2);
        float s1p = 0.5f * wp, s2p = 0.5f * hp;
        float cp = cosf(r_p), sp = sinf(r_p);

        // target box
        float xt = target[5 * b + 0];
        float yt = target[5 * b + 1];
        float wt = clip_wh(target[5 * b + 2]);
        float ht = clip_wh(target[5 * b + 3]);
        float r_t = target[5 * b + 4] * (CUDART_PI_F / 180.0f);
        float s1t = 0.5f * wt, s2t = 0.5f * ht;
        float ct = cosf(r_t), st = sinf(r_t);

        float dx = xp - xt, dy = yp - yt;
        float xy_dist = dx * dx + dy * dy;

        // Sigma = R diag(s^2) R^T for 2x2: closed form
        float sp1_2 = s1p * s1p, sp2_2 = s2p * s2p;
        float st1_2 = s1t * s1t, st2_2 = s2t * s2t;

        float Ap = sp1_2 * cp * cp + sp2_2 * sp * sp;
        float Bp = sp1_2 * sp * sp + sp2_2 * cp * cp;
        float Cp = (sp1_2 - sp2_2) * cp * sp;

        float At = st1_2 * ct * ct + st2_2 * st * st;
        float Bt = st1_2 * st * st + st2_2 * ct * ct;
        float Ct = (st1_2 - st2_2) * ct * st;

        float tr_pt = Ap * At + Bp * Bt + 2.0f * Cp * Ct;
        float det_sqrt = sqrtf(fmaxf(s1p * s2p * s1t * s2t, 0.0f));

        float whr = sp1_2 + sp2_2 + st1_2 + st2_2
                  - 2.0f * sqrtf(fmaxf(tr_pt + 2.0f * det_sqrt, 0.0f));

        float dist = fmaxf(xy_dist + whr, 0.0f);
        float loss = 1.0f - 1.0f / (1.0f + dist);
        g_partial[b] = loss;
    }
}

// Deterministic single-block mean over B partial losses.
__global__ void __launch_bounds__(THREADS)
gwd_reduce_kernel(float* __restrict__ out, int B)
{
    const int t = threadIdx.x;
    float acc = 0.0f;
    for (int i = t; i < B; i += THREADS) acc += g_partial[i];

    __shared__ float sh[THREADS];
    sh[t] = acc;
    __syncthreads();
    #pragma unroll
    for (int s = THREADS / 2; s > 0; s >>= 1) {
        if (t < s) sh[t] += sh[t + s];
        __syncthreads();
    }
    if (t == 0) out[0] = sh[0] / (float)B;
}

extern "C" void kernel_launch(void* const* d_in, const int* in_sizes, int n_in,
                              void* d_out, int out_size)
{
    const float* hm     = (const float*)d_in[0];  // (B,1,H,W)
    const float* ab     = (const float*)d_in[1];  // (B,2,H,W)
    const float* trig   = (const float*)d_in[2];  // (B,2,H,W)
    const float* center = (const float*)d_in[3];  // (B,2)
    const float* target = (const float*)d_in[4];  // (B,5)
    float* out = (float*)d_out;

    const int B  = in_sizes[4] / 5;
    const int HW = in_sizes[0] / B;

    gwd_main_kernel<<<B, THREADS>>>(hm, ab, trig, center, target, HW);
    gwd_reduce_kernel<<<1, THREADS>>>(out, B);
}